// round 14
// baseline (speedup 1.0000x reference)
#include <cuda_runtime.h>
#include <cuda_bf16.h>
#include <cstdint>

#define P 12
#define H 128
#define DIN 32
#define NB 8
#define NROWSB (NB*P)         // 96 rows, 6 m-tiles
#define THREADS 384
#define STRIDE 272            // B tile bytes/row: 128 bf16 + 8 pad
#define ZSTRIDE 136           // z scratch floats/row: 128 + 8 pad

// ---------------- SMEM byte offsets (R12 layout) ----------------
#define OFF_BH 0                              // h tile hi bf16 [96][STRIDE] = 26112
#define OFF_BL (OFF_BH + NROWSB*STRIDE)       // 26112
#define OFF_Z  (OFF_BL + NROWSB*STRIDE)       // 52224: fp32 z [96][ZSTRIDE]
#define OFF_AHAT (OFF_Z + NROWSB*ZSTRIDE*4)   // 104448
#define OFF_LON (OFF_AHAT + NB*144*4)         // 109056
#define OFF_DD  (OFF_LON + NROWSB*4)          // 109440
#define SMEM_BYTES (OFF_DD + NROWSB*4)        // 109824 -> 2 blocks/SM

#define OFF_G  (OFF_BL + 8192)
#define OFF_O1 (OFF_G + NB*H*4)

typedef unsigned long long ull;
typedef uint32_t u32;

// W fragment buffer: [l(4)][kt(8)][jf(16)][lane(32)] x uint4 {b0h,b1h,b0l,b1l}
__device__ __align__(16) unsigned char g_wbuf[4 * 8 * 16 * 32 * 16];

__device__ __forceinline__ void ffma2(ull& d, ull a, ull b) {
    asm volatile("fma.rn.f32x2 %0, %1, %2, %0;" : "+l"(d) : "l"(a), "l"(b));
}
__device__ __forceinline__ ull pack2f(float x, float y) {
    ull r; asm("mov.b64 %0, {%1, %2};" : "=l"(r) : "f"(x), "f"(y)); return r;
}
__device__ __forceinline__ float2 unpack2(ull v) {
    float2 f; asm("mov.b64 {%0, %1}, %2;" : "=f"(f.x), "=f"(f.y) : "l"(v)); return f;
}
__device__ __forceinline__ void mma16816(float c[4], const u32 a[4], u32 b0, u32 b1) {
    asm volatile("mma.sync.aligned.m16n8k16.row.col.f32.bf16.bf16.f32 "
                 "{%0,%1,%2,%3}, {%4,%5,%6,%7}, {%8,%9}, {%0,%1,%2,%3};"
                 : "+f"(c[0]), "+f"(c[1]), "+f"(c[2]), "+f"(c[3])
                 : "r"(a[0]), "r"(a[1]), "r"(a[2]), "r"(a[3]), "r"(b0), "r"(b1));
}
__device__ __forceinline__ void ldsm4(u32 r[4], u32 addr) {
    asm volatile("ldmatrix.sync.aligned.m8n8.x4.shared.b16 {%0,%1,%2,%3}, [%4];"
        : "=r"(r[0]), "=r"(r[1]), "=r"(r[2]), "=r"(r[3]) : "r"(addr));
}
__device__ __forceinline__ u32 packbf(__nv_bfloat16 a, __nv_bfloat16 b) {
    return (u32)__bfloat16_as_ushort(a) | ((u32)__bfloat16_as_ushort(b) << 16);
}
__device__ __forceinline__ u32 smem_u32(const void* p) {
    u32 a;
    asm("{ .reg .u64 t; cvta.to.shared.u64 t, %1; cvt.u32.u64 %0, t; }" : "=r"(a) : "l"(p));
    return a;
}

// ---------------- pre-kernel: fp32 W -> split-bf16 mma fragments ----------------
__global__ void conv_w_kernel(const float* __restrict__ W_in,
                              const float* __restrict__ W_gcn)
{
    const int idx = blockIdx.x * 256 + threadIdx.x;   // 16384 total
    const int lane = idx & 31;
    const int jf   = (idx >> 5) & 15;
    const int kt   = (idx >> 9) & 7;
    const int l    = idx >> 12;
    if (l == 0 && kt >= 2) return;
    const int quad = lane >> 2, tq = lane & 3;
    const int j  = 8 * jf + quad;
    const int k0 = 16 * kt + 2 * tq;
    const float* W = (l == 0) ? W_in : (W_gcn + (l - 1) * H * H);
    const float w00 = W[k0 * H + j],       w01 = W[(k0 + 1) * H + j];
    const float w10 = W[(k0 + 8) * H + j], w11 = W[(k0 + 9) * H + j];
    const __nv_bfloat16 h00 = __float2bfloat16(w00), h01 = __float2bfloat16(w01);
    const __nv_bfloat16 h10 = __float2bfloat16(w10), h11 = __float2bfloat16(w11);
    uint4 v;
    v.x = packbf(h00, h01);
    v.y = packbf(h10, h11);
    v.z = packbf(__float2bfloat16(w00 - __bfloat162float(h00)),
                 __float2bfloat16(w01 - __bfloat162float(h01)));
    v.w = packbf(__float2bfloat16(w10 - __bfloat162float(h10)),
                 __float2bfloat16(w11 - __bfloat162float(h11)));
    *(uint4*)(g_wbuf + (u32)((((l * 8 + kt) * 16 + jf) * 32 + lane)) * 16) = v;
}

extern __shared__ char smem[];

__device__ __forceinline__ void stHL_B(u32 byte, float v) {
    __nv_bfloat16 hi = __float2bfloat16(v);
    *(__nv_bfloat16*)(smem + OFF_BH + byte) = hi;
    *(__nv_bfloat16*)(smem + OFF_BL + byte) = __float2bfloat16(v - __bfloat162float(hi));
}

__global__ __launch_bounds__(THREADS, 2)
void gnn_hmma9_kernel(const float* __restrict__ x,
                      const float* __restrict__ b_in,
                      const float* __restrict__ b_gcn,
                      const float* __restrict__ W_out1,
                      const float* __restrict__ b_out1,
                      const float* __restrict__ W_out2,
                      const float* __restrict__ b_out2,
                      float* __restrict__ out,
                      int B)
{
    const int tid  = threadIdx.x;
    const int wid  = tid >> 5, lane = tid & 31;
    const int quad = lane >> 2, tq = lane & 3;
    const int mg   = wid / 4;                // 0..2: m-tiles {mg, mg+3}
    const int ng   = wid & 3;                // 0..3: cols [32ng, 32ng+32)
    const long b0  = (long)blockIdx.x * NB;
    const int  nb  = (B - b0 < NB) ? (int)(B - b0) : NB;

    const u32 sbase = smem_u32(smem);
    const u32 a_lane = (u32)((lane & 7) + 8 * ((lane >> 3) & 1)) * STRIDE + (u32)(lane >> 4) * 16;

    float* zf   = (float*)(smem + OFF_Z);
    float* lonF = (float*)(smem + OFF_LON);
    float* dF   = (float*)(smem + OFF_DD);
    float* ahat = (float*)(smem + OFF_AHAT);

    // ---------------- stage x into h tile (hi/lo), save longitudes ----------------
    for (int i = tid; i < NROWSB * DIN; i += THREADS) {
        const int r = i >> 5, k = i & 31;
        const float v = (r < nb * P) ? x[b0 * (P * DIN) + i] : 0.f;
        stHL_B((u32)r * STRIDE + (u32)k * 2, v);
        if (k == 0 && r < nb * P) lonF[r] = v;
    }
    __syncthreads();

    // ---------------- adjacency ----------------
    float arow[P];
    if (tid < nb * P) {
        const int g = tid / P;
        const float lp = lonF[tid];
        float deg = 0.f;
        #pragma unroll
        for (int q = 0; q < P; q++) {
            const float lq = lonF[g * P + q];
            float d = fmodf(fabsf(lp - lq), 360.0f);
            float dist = fminf(d, 360.0f - d);
            float a = (dist < 10.0f) ? 1.0f : 0.0f;
            if (q == (tid - g * P)) a += 1.0f;
            arow[q] = a; deg += a;
        }
        dF[tid] = rsqrtf(fmaxf(deg, 1e-12f));
    }
    __syncthreads();
    if (tid < nb * P) {
        const int g = tid / P, p = tid - g * P;
        const float dp = dF[tid];
        #pragma unroll
        for (int q = 0; q < P; q++)
            ahat[(g * P + p) * P + q] = arow[q] * dp * dF[g * P + q];
    }
    __syncthreads();                          // staging + ahat visible

    float c[2][4][4];

    // ---------------- 4 rounds: input proj + 3 GCN layers ----------------
    #pragma unroll 1
    for (int round = 0; round < 4; round++) {
        #pragma unroll
        for (int tl = 0; tl < 2; tl++)
            #pragma unroll
            for (int f = 0; f < 4; f++) {
                c[tl][f][0] = 0.f; c[tl][f][1] = 0.f; c[tl][f][2] = 0.f; c[tl][f][3] = 0.f;
            }

        const int kmax = (round == 0) ? 2 : 8;
        // 32-bit offset into g_wbuf for this (round, ng, lane); kt stride = 8192 B
        const u32 woff0 = ((u32)((round * 8 * 16 + 4 * ng) * 32 + lane)) * 16u;
        const unsigned char* wbp = g_wbuf + woff0;

        // ---- software-pipelined k-loop: prefetch kt+1's W frags before kt's MMAs ----
        uint4 wf0 = *(const uint4*)(wbp);
        uint4 wf1 = *(const uint4*)(wbp + 512);
        uint4 wf2 = *(const uint4*)(wbp + 1024);
        uint4 wf3 = *(const uint4*)(wbp + 1536);
        #pragma unroll 1
        for (int kt = 0; kt < kmax; kt++) {
            const u32 kb = (u32)kt * 32;
            // current fragments
            const uint4 c0v = wf0, c1v = wf1, c2v = wf2, c3v = wf3;
            // prefetch next iteration (dead in last iteration but harmless in-bounds
            // for kt<7; clamp to current for kt==kmax-1)
            const u32 nkb = (kt + 1 < kmax) ? (u32)(kt + 1) * 8192u : (u32)kt * 8192u;
            wf0 = *(const uint4*)(wbp + nkb);
            wf1 = *(const uint4*)(wbp + nkb + 512);
            wf2 = *(const uint4*)(wbp + nkb + 1024);
            wf3 = *(const uint4*)(wbp + nkb + 1536);
            #pragma unroll
            for (int tl = 0; tl < 2; tl++) {
                const u32 rbase = (u32)(16 * (mg + 3 * tl)) * STRIDE + a_lane + kb;
                u32 ah[4], al[4];
                ldsm4(ah, sbase + OFF_BH + rbase);
                ldsm4(al, sbase + OFF_BL + rbase);
                mma16816(c[tl][0], ah, c0v.x, c0v.y);
                mma16816(c[tl][0], ah, c0v.z, c0v.w);
                mma16816(c[tl][0], al, c0v.x, c0v.y);
                mma16816(c[tl][1], ah, c1v.x, c1v.y);
                mma16816(c[tl][1], ah, c1v.z, c1v.w);
                mma16816(c[tl][1], al, c1v.x, c1v.y);
                mma16816(c[tl][2], ah, c2v.x, c2v.y);
                mma16816(c[tl][2], ah, c2v.z, c2v.w);
                mma16816(c[tl][2], al, c2v.x, c2v.y);
                mma16816(c[tl][3], ah, c3v.x, c3v.y);
                mma16816(c[tl][3], ah, c3v.z, c3v.w);
                mma16816(c[tl][3], al, c3v.x, c3v.y);
            }
        }

        if (round == 0) {
            // ---- round 0: bias + split-bf16 straight back into B tile ----
            __syncthreads();                  // all MMA reads of B done
            #pragma unroll
            for (int f = 0; f < 4; f++) {
                const int j0 = 32 * ng + 8 * f + 2 * tq;
                const float bb0 = b_in[j0], bb1 = b_in[j0 + 1];
                #pragma unroll
                for (int tl = 0; tl < 2; tl++) {
                    const int t = mg + 3 * tl;
                    const float v0 = c[tl][f][0] + bb0, v1 = c[tl][f][1] + bb1;
                    const float v2 = c[tl][f][2] + bb0, v3 = c[tl][f][3] + bb1;
                    const u32 rb = (u32)(16 * t + quad) * STRIDE + (u32)j0 * 2;
                    const __nv_bfloat16 h0 = __float2bfloat16(v0), h1 = __float2bfloat16(v1);
                    const __nv_bfloat16 h2 = __float2bfloat16(v2), h3 = __float2bfloat16(v3);
                    *(u32*)(smem + OFF_BH + rb)              = packbf(h0, h1);
                    *(u32*)(smem + OFF_BH + rb + 8 * STRIDE) = packbf(h2, h3);
                    *(u32*)(smem + OFF_BL + rb) =
                        packbf(__float2bfloat16(v0 - __bfloat162float(h0)),
                               __float2bfloat16(v1 - __bfloat162float(h1)));
                    *(u32*)(smem + OFF_BL + rb + 8 * STRIDE) =
                        packbf(__float2bfloat16(v2 - __bfloat162float(h2)),
                               __float2bfloat16(v3 - __bfloat162float(h3)));
                }
            }
            __syncthreads();
        } else {
            // ---- epilogue: fp32 z to scratch (writes Z only; MMA reads B only) ----
            #pragma unroll
            for (int f = 0; f < 4; f++) {
                const int j0 = 32 * ng + 8 * f + 2 * tq;
                #pragma unroll
                for (int tl = 0; tl < 2; tl++) {
                    const int t = mg + 3 * tl;
                    *(float2*)&zf[(16 * t + quad) * ZSTRIDE + j0] =
                        make_float2(c[tl][f][0], c[tl][f][1]);
                    *(float2*)&zf[(16 * t + quad + 8) * ZSTRIDE + j0] =
                        make_float2(c[tl][f][2], c[tl][f][3]);
                }
            }
            __syncthreads();                   // Z complete; all B reads done

            // ---- mix: h = relu(Ahat @ z + b); item = (graph g, col pair j,j+1) ----
            const float* bgp = b_gcn + (round - 1) * H;
            #pragma unroll 1
            for (int it = tid; it < nb * 64; it += THREADS) {
                const int g = it >> 6, jp = it & 63, j = 2 * jp;
                ull z2[P];
                #pragma unroll
                for (int p = 0; p < P; p++)
                    z2[p] = *(const ull*)&zf[(g * P + p) * ZSTRIDE + j];
                ull zqA[6], zqB[6];
                #pragma unroll
                for (int i2 = 0; i2 < 6; i2++) {
                    const float2 e = unpack2(z2[2 * i2]), o = unpack2(z2[2 * i2 + 1]);
                    zqA[i2] = pack2f(e.x, o.x);
                    zqB[i2] = pack2f(e.y, o.y);
                }
                const float2 bg = *(const float2*)&bgp[j];
                const float* Ag = ahat + g * 144;
                const u32 bbase = (u32)(g * P) * STRIDE + (u32)j * 2;
                float poolA = 0.f, poolB = 0.f;
                #pragma unroll
                for (int p = 0; p < P; p++) {
                    const ulonglong2* ap = (const ulonglong2*)(Ag + p * 12);
                    const ulonglong2 u0 = ap[0], u1 = ap[1], u2 = ap[2];
                    ull oA = 0ull, oB = 0ull;
                    ffma2(oA, u0.x, zqA[0]); ffma2(oB, u0.x, zqB[0]);
                    ffma2(oA, u0.y, zqA[1]); ffma2(oB, u0.y, zqB[1]);
                    ffma2(oA, u1.x, zqA[2]); ffma2(oB, u1.x, zqB[2]);
                    ffma2(oA, u1.y, zqA[3]); ffma2(oB, u1.y, zqB[3]);
                    ffma2(oA, u2.x, zqA[4]); ffma2(oB, u2.x, zqB[4]);
                    ffma2(oA, u2.y, zqA[5]); ffma2(oB, u2.y, zqB[5]);
                    const float2 sA = unpack2(oA), sB = unpack2(oB);
                    const float vA = fmaxf(sA.x + sA.y + bg.x, 0.f);
                    const float vB = fmaxf(sB.x + sB.y + bg.y, 0.f);
                    if (round < 3) {
                        const __nv_bfloat16 hA = __float2bfloat16(vA), hB = __float2bfloat16(vB);
                        const u32 byte = bbase + (u32)p * STRIDE;
                        *(u32*)(smem + OFF_BH + byte) = packbf(hA, hB);
                        *(u32*)(smem + OFF_BL + byte) =
                            packbf(__float2bfloat16(vA - __bfloat162float(hA)),
                                   __float2bfloat16(vB - __bfloat162float(hB)));
                    } else {
                        poolA += vA; poolB += vB;
                    }
                }
                if (round == 3)
                    *(float2*)&((float*)(smem + OFF_G))[g * H + j] =
                        make_float2(poolA * (1.0f / 12.0f), poolB * (1.0f / 12.0f));
            }
            __syncthreads();                   // B / G ready
        }
    }

    // ---------------- head: g -> relu(g@W1+b1) -> @W2+b2 ----------------
    float* wv  = (float*)(smem + OFF_BH);      // [128][64] fp32; G/O1 live above
    float* sG  = (float*)(smem + OFF_G);
    float* sO1 = (float*)(smem + OFF_O1);
    for (int i = tid; i < H * 64; i += THREADS) wv[i] = W_out1[i];
    __syncthreads();
    for (int i = tid; i < nb * 64; i += THREADS) {
        const int bb = i >> 6, m = i & 63;
        float s = b_out1[m];
        const float* gr = sG + bb * H;
        #pragma unroll 8
        for (int k = 0; k < H; k++) s = fmaf(gr[k], wv[k * 64 + m], s);
        sO1[i] = fmaxf(s, 0.f);
    }
    __syncthreads();
    if (tid < nb * 3) {
        const int bb = tid / 3, d = tid - bb * 3;
        float s = b_out2[d];
        const float* o1 = sO1 + bb * 64;
        #pragma unroll
        for (int m = 0; m < 64; m++) s = fmaf(o1[m], W_out2[m * 3 + d], s);
        out[(b0 + bb) * 3 + d] = s;
    }
}

extern "C" void kernel_launch(void* const* d_in, const int* in_sizes, int n_in,
                              void* d_out, int out_size)
{
    const float* x      = (const float*)d_in[0];
    const float* W_in   = (const float*)d_in[1];
    const float* b_in   = (const float*)d_in[2];
    const float* W_gcn  = (const float*)d_in[3];
    const float* b_gcn  = (const float*)d_in[4];
    const float* W_out1 = (const float*)d_in[5];
    const float* b_out1 = (const float*)d_in[6];
    const float* W_out2 = (const float*)d_in[7];
    const float* b_out2 = (const float*)d_in[8];
    float* out = (float*)d_out;

    const int B = in_sizes[0] / (P * DIN);
    const int blocks = (B + NB - 1) / NB;

    conv_w_kernel<<<64, 256>>>(W_in, W_gcn);

    cudaFuncSetAttribute(gnn_hmma9_kernel,
                         cudaFuncAttributeMaxDynamicSharedMemorySize, SMEM_BYTES);
    gnn_hmma9_kernel<<<blocks, THREADS, SMEM_BYTES>>>(
        x, b_in, b_gcn, W_out1, b_out1, W_out2, b_out2, out, B);
}

// round 15
// speedup vs baseline: 1.0198x; 1.0198x over previous
#include <cuda_runtime.h>
#include <cuda_bf16.h>
#include <cstdint>

#define P 12
#define H 128
#define DIN 32
#define NB 8
#define NROWSB (NB*P)         // 96 rows, 6 m-tiles
#define THREADS 384
#define STRIDE 272            // B tile bytes/row: 128 bf16 + 8 pad
#define ZR2 97                // ztp row stride in float2 units (96 rows + 1 pad)

// ---------------- SMEM byte offsets ----------------
#define OFF_BH 0                              // h tile hi bf16 [96][STRIDE] = 26112
#define OFF_BL (OFF_BH + NROWSB*STRIDE)       // 26112
#define OFF_ZT (OFF_BL + NROWSB*STRIDE)       // 52224: z col-pair float2 [64][ZR2] = 49664
#define OFF_AHAT2 (OFF_ZT + 64*ZR2*8)         // 101888: dup {a,a} ull [NB][12][12] = 9216
#define OFF_LON (OFF_AHAT2 + NB*144*8)        // 111104
#define OFF_DD  (OFF_LON + NROWSB*4)          // 111488
#define SMEM_BYTES (OFF_DD + NROWSB*4)        // 111872 -> 2x(111872+1024)=225792: 2 blocks/SM

// G and O1 alias the B tile region (dead when they're live); head wv uses [0,32768)
#define OFF_G  (OFF_BL + 8192)
#define OFF_O1 (OFF_G + NB*H*4)

typedef unsigned long long ull;
typedef uint32_t u32;

// W fragment buffer: [l(4)][kt(8)][jf(16)][lane(32)] x uint4 {b0h,b1h,b0l,b1l}
__device__ __align__(16) unsigned char g_wbuf[4 * 8 * 16 * 32 * 16];

__device__ __forceinline__ void ffma2(ull& d, ull a, ull b) {
    asm volatile("fma.rn.f32x2 %0, %1, %2, %0;" : "+l"(d) : "l"(a), "l"(b));
}
__device__ __forceinline__ ull pack2f(float x, float y) {
    ull r; asm("mov.b64 %0, {%1, %2};" : "=l"(r) : "f"(x), "f"(y)); return r;
}
__device__ __forceinline__ float2 unpack2(ull v) {
    float2 f; asm("mov.b64 {%0, %1}, %2;" : "=f"(f.x), "=f"(f.y) : "l"(v)); return f;
}
__device__ __forceinline__ void mma16816(float c[4], const u32 a[4], u32 b0, u32 b1) {
    asm volatile("mma.sync.aligned.m16n8k16.row.col.f32.bf16.bf16.f32 "
                 "{%0,%1,%2,%3}, {%4,%5,%6,%7}, {%8,%9}, {%0,%1,%2,%3};"
                 : "+f"(c[0]), "+f"(c[1]), "+f"(c[2]), "+f"(c[3])
                 : "r"(a[0]), "r"(a[1]), "r"(a[2]), "r"(a[3]), "r"(b0), "r"(b1));
}
__device__ __forceinline__ void ldsm4(u32 r[4], u32 addr) {
    asm volatile("ldmatrix.sync.aligned.m8n8.x4.shared.b16 {%0,%1,%2,%3}, [%4];"
        : "=r"(r[0]), "=r"(r[1]), "=r"(r[2]), "=r"(r[3]) : "r"(addr));
}
__device__ __forceinline__ u32 packbf(__nv_bfloat16 a, __nv_bfloat16 b) {
    return (u32)__bfloat16_as_ushort(a) | ((u32)__bfloat16_as_ushort(b) << 16);
}
__device__ __forceinline__ u32 smem_u32(const void* p) {
    u32 a;
    asm("{ .reg .u64 t; cvta.to.shared.u64 t, %1; cvt.u32.u64 %0, t; }" : "=r"(a) : "l"(p));
    return a;
}

// ---------------- pre-kernel: fp32 W -> split-bf16 mma fragments ----------------
__global__ void conv_w_kernel(const float* __restrict__ W_in,
                              const float* __restrict__ W_gcn)
{
    const int idx = blockIdx.x * 256 + threadIdx.x;   // 16384 total
    const int lane = idx & 31;
    const int jf   = (idx >> 5) & 15;
    const int kt   = (idx >> 9) & 7;
    const int l    = idx >> 12;
    if (l == 0 && kt >= 2) return;
    const int quad = lane >> 2, tq = lane & 3;
    const int j  = 8 * jf + quad;
    const int k0 = 16 * kt + 2 * tq;
    const float* W = (l == 0) ? W_in : (W_gcn + (l - 1) * H * H);
    const float w00 = W[k0 * H + j],       w01 = W[(k0 + 1) * H + j];
    const float w10 = W[(k0 + 8) * H + j], w11 = W[(k0 + 9) * H + j];
    const __nv_bfloat16 h00 = __float2bfloat16(w00), h01 = __float2bfloat16(w01);
    const __nv_bfloat16 h10 = __float2bfloat16(w10), h11 = __float2bfloat16(w11);
    uint4 v;
    v.x = packbf(h00, h01);
    v.y = packbf(h10, h11);
    v.z = packbf(__float2bfloat16(w00 - __bfloat162float(h00)),
                 __float2bfloat16(w01 - __bfloat162float(h01)));
    v.w = packbf(__float2bfloat16(w10 - __bfloat162float(h10)),
                 __float2bfloat16(w11 - __bfloat162float(h11)));
    *(uint4*)(g_wbuf + (u32)((((l * 8 + kt) * 16 + jf) * 32 + lane)) * 16) = v;
}

extern __shared__ char smem[];

__device__ __forceinline__ void stHL_B(u32 byte, float v) {
    __nv_bfloat16 hi = __float2bfloat16(v);
    *(__nv_bfloat16*)(smem + OFF_BH + byte) = hi;
    *(__nv_bfloat16*)(smem + OFF_BL + byte) = __float2bfloat16(v - __bfloat162float(hi));
}

__global__ __launch_bounds__(THREADS, 2)
void gnn_hmma10_kernel(const float* __restrict__ x,
                       const float* __restrict__ b_in,
                       const float* __restrict__ b_gcn,
                       const float* __restrict__ W_out1,
                       const float* __restrict__ b_out1,
                       const float* __restrict__ W_out2,
                       const float* __restrict__ b_out2,
                       float* __restrict__ out,
                       int B)
{
    const int tid  = threadIdx.x;
    const int wid  = tid >> 5, lane = tid & 31;
    const int quad = lane >> 2, tq = lane & 3;
    const int mg   = wid / 4;                // 0..2: m-tiles {mg, mg+3}
    const int ng   = wid & 3;                // 0..3: cols [32ng, 32ng+32)
    const long b0  = (long)blockIdx.x * NB;
    const int  nb  = (B - b0 < NB) ? (int)(B - b0) : NB;

    const u32 sbase = smem_u32(smem);
    const u32 a_lane = (u32)((lane & 7) + 8 * ((lane >> 3) & 1)) * STRIDE + (u32)(lane >> 4) * 16;

    float2* ztp  = (float2*)(smem + OFF_ZT);
    ull*  ahat2  = (ull*)(smem + OFF_AHAT2);
    float* lonF  = (float*)(smem + OFF_LON);
    float* dF    = (float*)(smem + OFF_DD);

    // ---------------- stage x into h tile (hi/lo), save longitudes ----------------
    for (int i = tid; i < NROWSB * DIN; i += THREADS) {
        const int r = i >> 5, k = i & 31;
        const float v = (r < nb * P) ? x[b0 * (P * DIN) + i] : 0.f;
        stHL_B((u32)r * STRIDE + (u32)k * 2, v);
        if (k == 0 && r < nb * P) lonF[r] = v;
    }
    __syncthreads();

    // ---------------- adjacency (duplicated {a,a} layout) ----------------
    float arow[P];
    if (tid < nb * P) {
        const int g = tid / P;
        const float lp = lonF[tid];
        float deg = 0.f;
        #pragma unroll
        for (int q = 0; q < P; q++) {
            const float lq = lonF[g * P + q];
            float d = fmodf(fabsf(lp - lq), 360.0f);
            float dist = fminf(d, 360.0f - d);
            float a = (dist < 10.0f) ? 1.0f : 0.0f;
            if (q == (tid - g * P)) a += 1.0f;
            arow[q] = a; deg += a;
        }
        dF[tid] = rsqrtf(fmaxf(deg, 1e-12f));
    }
    __syncthreads();
    if (tid < nb * P) {
        const int g = tid / P;
        const float dp = dF[tid];
        #pragma unroll
        for (int q = 0; q < P; q++) {
            const float a = arow[q] * dp * dF[g * P + q];
            ahat2[tid * 12 + q] = pack2f(a, a);
        }
    }
    __syncthreads();                          // staging + ahat2 visible

    float c[2][4][4];

    // ---------------- 4 rounds: input proj + 3 GCN layers ----------------
    #pragma unroll 1
    for (int round = 0; round < 4; round++) {
        #pragma unroll
        for (int tl = 0; tl < 2; tl++)
            #pragma unroll
            for (int f = 0; f < 4; f++) {
                c[tl][f][0] = 0.f; c[tl][f][1] = 0.f; c[tl][f][2] = 0.f; c[tl][f][3] = 0.f;
            }

        const int kmax = (round == 0) ? 2 : 8;
        const unsigned char* wb = g_wbuf
            + (u32)(((round * 8) * 16 + 4 * ng) * 32 + lane) * 16u;
        #pragma unroll 1
        for (int kt = 0; kt < kmax; kt++) {
            const u32 kb = (u32)kt * 32;
            uint4 wf0 = *(const uint4*)(wb + (u32)kt * 8192u);
            uint4 wf1 = *(const uint4*)(wb + (u32)kt * 8192u + 512);
            uint4 wf2 = *(const uint4*)(wb + (u32)kt * 8192u + 1024);
            uint4 wf3 = *(const uint4*)(wb + (u32)kt * 8192u + 1536);
            #pragma unroll
            for (int tl = 0; tl < 2; tl++) {
                const u32 rbase = (u32)(16 * (mg + 3 * tl)) * STRIDE + a_lane + kb;
                u32 ah[4], al[4];
                ldsm4(ah, sbase + OFF_BH + rbase);
                ldsm4(al, sbase + OFF_BL + rbase);
                mma16816(c[tl][0], ah, wf0.x, wf0.y);
                mma16816(c[tl][0], ah, wf0.z, wf0.w);
                mma16816(c[tl][0], al, wf0.x, wf0.y);
                mma16816(c[tl][1], ah, wf1.x, wf1.y);
                mma16816(c[tl][1], ah, wf1.z, wf1.w);
                mma16816(c[tl][1], al, wf1.x, wf1.y);
                mma16816(c[tl][2], ah, wf2.x, wf2.y);
                mma16816(c[tl][2], ah, wf2.z, wf2.w);
                mma16816(c[tl][2], al, wf2.x, wf2.y);
                mma16816(c[tl][3], ah, wf3.x, wf3.y);
                mma16816(c[tl][3], ah, wf3.z, wf3.w);
                mma16816(c[tl][3], al, wf3.x, wf3.y);
            }
        }

        if (round == 0) {
            // ---- round 0: bias + split-bf16 straight back into B tile ----
            __syncthreads();                  // all MMA reads of B done
            #pragma unroll
            for (int f = 0; f < 4; f++) {
                const int j0 = 32 * ng + 8 * f + 2 * tq;
                const float bb0 = b_in[j0], bb1 = b_in[j0 + 1];
                #pragma unroll
                for (int tl = 0; tl < 2; tl++) {
                    const int t = mg + 3 * tl;
                    const float v0 = c[tl][f][0] + bb0, v1 = c[tl][f][1] + bb1;
                    const float v2 = c[tl][f][2] + bb0, v3 = c[tl][f][3] + bb1;
                    const u32 rb = (u32)(16 * t + quad) * STRIDE + (u32)j0 * 2;
                    const __nv_bfloat16 h0 = __float2bfloat16(v0), h1 = __float2bfloat16(v1);
                    const __nv_bfloat16 h2 = __float2bfloat16(v2), h3 = __float2bfloat16(v3);
                    *(u32*)(smem + OFF_BH + rb)              = packbf(h0, h1);
                    *(u32*)(smem + OFF_BH + rb + 8 * STRIDE) = packbf(h2, h3);
                    *(u32*)(smem + OFF_BL + rb) =
                        packbf(__float2bfloat16(v0 - __bfloat162float(h0)),
                               __float2bfloat16(v1 - __bfloat162float(h1)));
                    *(u32*)(smem + OFF_BL + rb + 8 * STRIDE) =
                        packbf(__float2bfloat16(v2 - __bfloat162float(h2)),
                               __float2bfloat16(v3 - __bfloat162float(h3)));
                }
            }
            __syncthreads();
        } else {
            // ---- epilogue: z in col-pair layout (natural accumulator shape).
            //      Writes ZT only; no barrier needed vs MMA (reads B only). ----
            #pragma unroll
            for (int f = 0; f < 4; f++) {
                const int jp0 = 16 * ng + 4 * f + tq;          // column-pair index
                #pragma unroll
                for (int tl = 0; tl < 2; tl++) {
                    const int r0 = 16 * (mg + 3 * tl) + quad;
                    ztp[jp0 * ZR2 + r0]     = make_float2(c[tl][f][0], c[tl][f][1]);
                    ztp[jp0 * ZR2 + r0 + 8] = make_float2(c[tl][f][2], c[tl][f][3]);
                }
            }
            __syncthreads();                   // ZT complete; all B reads done

            // ---- mix: h = relu(Ahat @ z + b); item = (graph g, col pair jp) ----
            const float* bgp = b_gcn + (round - 1) * H;
            #pragma unroll 1
            for (int it = tid; it < nb * 64; it += THREADS) {
                const int g = it >> 6, jp = it & 63, j = 2 * jp;
                const ull* zr = (const ull*)(ztp + (jp * ZR2 + 12 * g));
                ull zc[P];
                #pragma unroll
                for (int q = 0; q < P; q++) zc[q] = zr[q];
                const float2 bg = *(const float2*)&bgp[j];
                const ull bseed = pack2f(bg.x, bg.y);
                const ull* A2 = ahat2 + g * 144;
                const u32 bbase = (u32)(g * P) * STRIDE + (u32)j * 2;
                float poolA = 0.f, poolB = 0.f;
                #pragma unroll
                for (int p = 0; p < P; p++) {
                    const ulonglong2* ap = (const ulonglong2*)(A2 + p * 12);
                    const ulonglong2 u0 = ap[0], u1 = ap[1], u2 = ap[2];
                    const ulonglong2 u3 = ap[3], u4 = ap[4], u5 = ap[5];
                    ull o = bseed;
                    ffma2(o, u0.x, zc[0]);  ffma2(o, u0.y, zc[1]);
                    ffma2(o, u1.x, zc[2]);  ffma2(o, u1.y, zc[3]);
                    ffma2(o, u2.x, zc[4]);  ffma2(o, u2.y, zc[5]);
                    ffma2(o, u3.x, zc[6]);  ffma2(o, u3.y, zc[7]);
                    ffma2(o, u4.x, zc[8]);  ffma2(o, u4.y, zc[9]);
                    ffma2(o, u5.x, zc[10]); ffma2(o, u5.y, zc[11]);
                    const float2 v = unpack2(o);
                    const float vA = fmaxf(v.x, 0.f), vB = fmaxf(v.y, 0.f);
                    if (round < 3) {
                        const __nv_bfloat16 hA = __float2bfloat16(vA), hB = __float2bfloat16(vB);
                        const u32 byte = bbase + (u32)p * STRIDE;
                        *(u32*)(smem + OFF_BH + byte) = packbf(hA, hB);
                        *(u32*)(smem + OFF_BL + byte) =
                            packbf(__float2bfloat16(vA - __bfloat162float(hA)),
                                   __float2bfloat16(vB - __bfloat162float(hB)));
                    } else {
                        poolA += vA; poolB += vB;
                    }
                }
                if (round == 3)
                    *(float2*)&((float*)(smem + OFF_G))[g * H + j] =
                        make_float2(poolA * (1.0f / 12.0f), poolB * (1.0f / 12.0f));
            }
            __syncthreads();                   // B / G ready
        }
    }

    // ---------------- head: g -> relu(g@W1+b1) -> @W2+b2 ----------------
    float* wv  = (float*)(smem + OFF_BH);      // [128][64] fp32; G/O1 live above 32768
    float* sG  = (float*)(smem + OFF_G);
    float* sO1 = (float*)(smem + OFF_O1);
    for (int i = tid; i < H * 64; i += THREADS) wv[i] = W_out1[i];
    __syncthreads();
    for (int i = tid; i < nb * 64; i += THREADS) {
        const int bb = i >> 6, m = i & 63;
        float s = b_out1[m];
        const float* gr = sG + bb * H;
        #pragma unroll 8
        for (int k = 0; k < H; k++) s = fmaf(gr[k], wv[k * 64 + m], s);
        sO1[i] = fmaxf(s, 0.f);
    }
    __syncthreads();
    if (tid < nb * 3) {
        const int bb = tid / 3, d = tid - bb * 3;
        float s = b_out2[d];
        const float* o1 = sO1 + bb * 64;
        #pragma unroll
        for (int m = 0; m < 64; m++) s = fmaf(o1[m], W_out2[m * 3 + d], s);
        out[(b0 + bb) * 3 + d] = s;
    }
}

extern "C" void kernel_launch(void* const* d_in, const int* in_sizes, int n_in,
                              void* d_out, int out_size)
{
    const float* x      = (const float*)d_in[0];
    const float* W_in   = (const float*)d_in[1];
    const float* b_in   = (const float*)d_in[2];
    const float* W_gcn  = (const float*)d_in[3];
    const float* b_gcn  = (const float*)d_in[4];
    const float* W_out1 = (const float*)d_in[5];
    const float* b_out1 = (const float*)d_in[6];
    const float* W_out2 = (const float*)d_in[7];
    const float* b_out2 = (const float*)d_in[8];
    float* out = (float*)d_out;

    const int B = in_sizes[0] / (P * DIN);
    const int blocks = (B + NB - 1) / NB;

    conv_w_kernel<<<64, 256>>>(W_in, W_gcn);

    cudaFuncSetAttribute(gnn_hmma10_kernel,
                         cudaFuncAttributeMaxDynamicSharedMemorySize, SMEM_BYTES);
    gnn_hmma10_kernel<<<blocks, THREADS, SMEM_BYTES>>>(
        x, b_in, b_gcn, W_out1, b_out1, W_out2, b_out2, out, B);
}

// round 16
// speedup vs baseline: 1.0833x; 1.0622x over previous
#include <cuda_runtime.h>
#include <cuda_bf16.h>
#include <cstdint>

#define P 12
#define H 128
#define DIN 32
#define NB 8
#define NROWSB (NB*P)         // 96 rows, 6 m-tiles
#define THREADS 384
#define STRIDE 272            // B tile bytes/row: 128 bf16 + 8 pad
#define ZR2 99                // ztp row stride in float2 units (96 rows + 3 pad; 2-way banks both ways)

// ---------------- SMEM byte offsets ----------------
#define OFF_BH 0                              // h tile hi bf16 [96][STRIDE] = 26112
#define OFF_BL (OFF_BH + NROWSB*STRIDE)       // 26112
#define OFF_ZT (OFF_BL + NROWSB*STRIDE)       // 52224: z col-pair float2 [64][ZR2] = 50688
#define OFF_AHAT2 (OFF_ZT + 64*ZR2*8)         // 102912: dup {a,a} ull [NB][12][12] = 9216
#define OFF_LON (OFF_AHAT2 + NB*144*8)        // 112128
#define OFF_DD  (OFF_LON + NROWSB*4)          // 112512
#define SMEM_BYTES (OFF_DD + NROWSB*4)        // 112896 -> 2x(112896+1024)=227840: 2 blocks/SM

// G and O1 alias the B tile region (dead when they're live); head wv uses [0,32768)
#define OFF_G  (OFF_BL + 8192)
#define OFF_O1 (OFF_G + NB*H*4)

typedef unsigned long long ull;
typedef uint32_t u32;

// W fragment buffer: [l(4)][kt(8)][jf(16)][lane(32)] x uint4 {b0h,b1h,b0l,b1l}
__device__ __align__(16) unsigned char g_wbuf[4 * 8 * 16 * 32 * 16];

__device__ __forceinline__ void ffma2(ull& d, ull a, ull b) {
    asm volatile("fma.rn.f32x2 %0, %1, %2, %0;" : "+l"(d) : "l"(a), "l"(b));
}
__device__ __forceinline__ ull pack2f(float x, float y) {
    ull r; asm("mov.b64 %0, {%1, %2};" : "=l"(r) : "f"(x), "f"(y)); return r;
}
__device__ __forceinline__ float2 unpack2(ull v) {
    float2 f; asm("mov.b64 {%0, %1}, %2;" : "=f"(f.x), "=f"(f.y) : "l"(v)); return f;
}
__device__ __forceinline__ void mma16816(float c[4], const u32 a[4], u32 b0, u32 b1) {
    asm volatile("mma.sync.aligned.m16n8k16.row.col.f32.bf16.bf16.f32 "
                 "{%0,%1,%2,%3}, {%4,%5,%6,%7}, {%8,%9}, {%0,%1,%2,%3};"
                 : "+f"(c[0]), "+f"(c[1]), "+f"(c[2]), "+f"(c[3])
                 : "r"(a[0]), "r"(a[1]), "r"(a[2]), "r"(a[3]), "r"(b0), "r"(b1));
}
__device__ __forceinline__ void ldsm4(u32 r[4], u32 addr) {
    asm volatile("ldmatrix.sync.aligned.m8n8.x4.shared.b16 {%0,%1,%2,%3}, [%4];"
        : "=r"(r[0]), "=r"(r[1]), "=r"(r[2]), "=r"(r[3]) : "r"(addr));
}
__device__ __forceinline__ u32 packbf(__nv_bfloat16 a, __nv_bfloat16 b) {
    return (u32)__bfloat16_as_ushort(a) | ((u32)__bfloat16_as_ushort(b) << 16);
}
__device__ __forceinline__ u32 smem_u32(const void* p) {
    u32 a;
    asm("{ .reg .u64 t; cvta.to.shared.u64 t, %1; cvt.u32.u64 %0, t; }" : "=r"(a) : "l"(p));
    return a;
}

// ---------------- pre-kernel: fp32 W -> split-bf16 mma fragments ----------------
__global__ void conv_w_kernel(const float* __restrict__ W_in,
                              const float* __restrict__ W_gcn)
{
    const int idx = blockIdx.x * 256 + threadIdx.x;   // 16384 total
    const int lane = idx & 31;
    const int jf   = (idx >> 5) & 15;
    const int kt   = (idx >> 9) & 7;
    const int l    = idx >> 12;
    if (l == 0 && kt >= 2) return;
    const int quad = lane >> 2, tq = lane & 3;
    const int j  = 8 * jf + quad;
    const int k0 = 16 * kt + 2 * tq;
    const float* W = (l == 0) ? W_in : (W_gcn + (l - 1) * H * H);
    const float w00 = W[k0 * H + j],       w01 = W[(k0 + 1) * H + j];
    const float w10 = W[(k0 + 8) * H + j], w11 = W[(k0 + 9) * H + j];
    const __nv_bfloat16 h00 = __float2bfloat16(w00), h01 = __float2bfloat16(w01);
    const __nv_bfloat16 h10 = __float2bfloat16(w10), h11 = __float2bfloat16(w11);
    uint4 v;
    v.x = packbf(h00, h01);
    v.y = packbf(h10, h11);
    v.z = packbf(__float2bfloat16(w00 - __bfloat162float(h00)),
                 __float2bfloat16(w01 - __bfloat162float(h01)));
    v.w = packbf(__float2bfloat16(w10 - __bfloat162float(h10)),
                 __float2bfloat16(w11 - __bfloat162float(h11)));
    *(uint4*)(g_wbuf + (u32)((((l * 8 + kt) * 16 + jf) * 32 + lane)) * 16) = v;
}

extern __shared__ char smem[];

__device__ __forceinline__ void stHL_B(u32 byte, float v) {
    __nv_bfloat16 hi = __float2bfloat16(v);
    *(__nv_bfloat16*)(smem + OFF_BH + byte) = hi;
    *(__nv_bfloat16*)(smem + OFF_BL + byte) = __float2bfloat16(v - __bfloat162float(hi));
}

__global__ __launch_bounds__(THREADS, 2)
void gnn_hmma11_kernel(const float* __restrict__ x,
                       const float* __restrict__ b_in,
                       const float* __restrict__ b_gcn,
                       const float* __restrict__ W_out1,
                       const float* __restrict__ b_out1,
                       const float* __restrict__ W_out2,
                       const float* __restrict__ b_out2,
                       float* __restrict__ out,
                       int B)
{
    const int tid  = threadIdx.x;
    const int wid  = tid >> 5, lane = tid & 31;
    const int quad = lane >> 2, tq = lane & 3;
    const int mg   = wid / 4;                // 0..2: m-tiles {mg, mg+3}
    const int ng   = wid & 3;                // 0..3: cols [32ng, 32ng+32)
    const long b0  = (long)blockIdx.x * NB;
    const int  nb  = (B - b0 < NB) ? (int)(B - b0) : NB;

    const u32 sbase = smem_u32(smem);
    const u32 a_lane = (u32)((lane & 7) + 8 * ((lane >> 3) & 1)) * STRIDE + (u32)(lane >> 4) * 16;

    float2* ztp  = (float2*)(smem + OFF_ZT);
    ull*  ahat2  = (ull*)(smem + OFF_AHAT2);
    float* lonF  = (float*)(smem + OFF_LON);
    float* dF    = (float*)(smem + OFF_DD);

    // ---------------- stage x into h tile (hi/lo), save longitudes ----------------
    for (int i = tid; i < NROWSB * DIN; i += THREADS) {
        const int r = i >> 5, k = i & 31;
        const float v = (r < nb * P) ? x[b0 * (P * DIN) + i] : 0.f;
        stHL_B((u32)r * STRIDE + (u32)k * 2, v);
        if (k == 0 && r < nb * P) lonF[r] = v;
    }
    __syncthreads();

    // ---------------- adjacency (duplicated {a,a} layout) ----------------
    float arow[P];
    if (tid < nb * P) {
        const int g = tid / P;
        const float lp = lonF[tid];
        float deg = 0.f;
        #pragma unroll
        for (int q = 0; q < P; q++) {
            const float lq = lonF[g * P + q];
            float d = fmodf(fabsf(lp - lq), 360.0f);
            float dist = fminf(d, 360.0f - d);
            float a = (dist < 10.0f) ? 1.0f : 0.0f;
            if (q == (tid - g * P)) a += 1.0f;
            arow[q] = a; deg += a;
        }
        dF[tid] = rsqrtf(fmaxf(deg, 1e-12f));
    }
    __syncthreads();
    if (tid < nb * P) {
        const int g = tid / P;
        const float dp = dF[tid];
        #pragma unroll
        for (int q = 0; q < P; q++) {
            const float a = arow[q] * dp * dF[g * P + q];
            ahat2[tid * 12 + q] = pack2f(a, a);
        }
    }
    __syncthreads();                          // staging + ahat2 visible

    float c[2][4][4];

    // ---------------- 4 rounds: input proj + 3 GCN layers ----------------
    #pragma unroll 1
    for (int round = 0; round < 4; round++) {
        #pragma unroll
        for (int tl = 0; tl < 2; tl++)
            #pragma unroll
            for (int f = 0; f < 4; f++) {
                c[tl][f][0] = 0.f; c[tl][f][1] = 0.f; c[tl][f][2] = 0.f; c[tl][f][3] = 0.f;
            }

        const int kmax = (round == 0) ? 2 : 8;
        const unsigned char* wb = g_wbuf
            + (u32)(((round * 8) * 16 + 4 * ng) * 32 + lane) * 16u;
        #pragma unroll 1
        for (int kt = 0; kt < kmax; kt++) {
            const u32 kb = (u32)kt * 32;
            uint4 wf0 = *(const uint4*)(wb + (u32)kt * 8192u);
            uint4 wf1 = *(const uint4*)(wb + (u32)kt * 8192u + 512);
            uint4 wf2 = *(const uint4*)(wb + (u32)kt * 8192u + 1024);
            uint4 wf3 = *(const uint4*)(wb + (u32)kt * 8192u + 1536);
            #pragma unroll
            for (int tl = 0; tl < 2; tl++) {
                const u32 rbase = (u32)(16 * (mg + 3 * tl)) * STRIDE + a_lane + kb;
                u32 ah[4], al[4];
                ldsm4(ah, sbase + OFF_BH + rbase);
                ldsm4(al, sbase + OFF_BL + rbase);
                mma16816(c[tl][0], ah, wf0.x, wf0.y);
                mma16816(c[tl][0], ah, wf0.z, wf0.w);
                mma16816(c[tl][0], al, wf0.x, wf0.y);
                mma16816(c[tl][1], ah, wf1.x, wf1.y);
                mma16816(c[tl][1], ah, wf1.z, wf1.w);
                mma16816(c[tl][1], al, wf1.x, wf1.y);
                mma16816(c[tl][2], ah, wf2.x, wf2.y);
                mma16816(c[tl][2], ah, wf2.z, wf2.w);
                mma16816(c[tl][2], al, wf2.x, wf2.y);
                mma16816(c[tl][3], ah, wf3.x, wf3.y);
                mma16816(c[tl][3], ah, wf3.z, wf3.w);
                mma16816(c[tl][3], al, wf3.x, wf3.y);
            }
        }

        if (round == 0) {
            // ---- round 0: bias + split-bf16 straight back into B tile ----
            __syncthreads();                  // all MMA reads of B done
            #pragma unroll
            for (int f = 0; f < 4; f++) {
                const int j0 = 32 * ng + 8 * f + 2 * tq;
                const float bb0 = b_in[j0], bb1 = b_in[j0 + 1];
                #pragma unroll
                for (int tl = 0; tl < 2; tl++) {
                    const int t = mg + 3 * tl;
                    const float v0 = c[tl][f][0] + bb0, v1 = c[tl][f][1] + bb1;
                    const float v2 = c[tl][f][2] + bb0, v3 = c[tl][f][3] + bb1;
                    const u32 rb = (u32)(16 * t + quad) * STRIDE + (u32)j0 * 2;
                    const __nv_bfloat16 h0 = __float2bfloat16(v0), h1 = __float2bfloat16(v1);
                    const __nv_bfloat16 h2 = __float2bfloat16(v2), h3 = __float2bfloat16(v3);
                    *(u32*)(smem + OFF_BH + rb)              = packbf(h0, h1);
                    *(u32*)(smem + OFF_BH + rb + 8 * STRIDE) = packbf(h2, h3);
                    *(u32*)(smem + OFF_BL + rb) =
                        packbf(__float2bfloat16(v0 - __bfloat162float(h0)),
                               __float2bfloat16(v1 - __bfloat162float(h1)));
                    *(u32*)(smem + OFF_BL + rb + 8 * STRIDE) =
                        packbf(__float2bfloat16(v2 - __bfloat162float(h2)),
                               __float2bfloat16(v3 - __bfloat162float(h3)));
                }
            }
            __syncthreads();
        } else {
            // ---- epilogue: z in col-pair layout (natural accumulator shape).
            //      Writes ZT only; no barrier needed vs MMA (reads B only). ----
            #pragma unroll
            for (int f = 0; f < 4; f++) {
                const int jp0 = 16 * ng + 4 * f + tq;          // column-pair index
                #pragma unroll
                for (int tl = 0; tl < 2; tl++) {
                    const int r0 = 16 * (mg + 3 * tl) + quad;
                    ztp[jp0 * ZR2 + r0]     = make_float2(c[tl][f][0], c[tl][f][1]);
                    ztp[jp0 * ZR2 + r0 + 8] = make_float2(c[tl][f][2], c[tl][f][3]);
                }
            }
            __syncthreads();                   // ZT complete; all B reads done

            // ---- mix: h = relu(Ahat @ z + b); item = (graph g, col pair jp) ----
            const float* bgp = b_gcn + (round - 1) * H;
            #pragma unroll 1
            for (int it = tid; it < nb * 64; it += THREADS) {
                const int g = it >> 6, jp = it & 63, j = 2 * jp;
                const ull* zr = (const ull*)(ztp + (jp * ZR2 + 12 * g));
                ull zc[P];
                #pragma unroll
                for (int q = 0; q < P; q++) zc[q] = zr[q];
                const float2 bg = *(const float2*)&bgp[j];
                const ull bseed = pack2f(bg.x, bg.y);
                const ull* A2 = ahat2 + g * 144;
                const u32 bbase = (u32)(g * P) * STRIDE + (u32)j * 2;
                float poolA = 0.f, poolB = 0.f;
                #pragma unroll
                for (int p = 0; p < P; p++) {
                    const ulonglong2* ap = (const ulonglong2*)(A2 + p * 12);
                    const ulonglong2 u0 = ap[0], u1 = ap[1], u2 = ap[2];
                    const ulonglong2 u3 = ap[3], u4 = ap[4], u5 = ap[5];
                    ull o = bseed;
                    ffma2(o, u0.x, zc[0]);  ffma2(o, u0.y, zc[1]);
                    ffma2(o, u1.x, zc[2]);  ffma2(o, u1.y, zc[3]);
                    ffma2(o, u2.x, zc[4]);  ffma2(o, u2.y, zc[5]);
                    ffma2(o, u3.x, zc[6]);  ffma2(o, u3.y, zc[7]);
                    ffma2(o, u4.x, zc[8]);  ffma2(o, u4.y, zc[9]);
                    ffma2(o, u5.x, zc[10]); ffma2(o, u5.y, zc[11]);
                    const float2 v = unpack2(o);
                    const float vA = fmaxf(v.x, 0.f), vB = fmaxf(v.y, 0.f);
                    if (round < 3) {
                        const __nv_bfloat16 hA = __float2bfloat16(vA), hB = __float2bfloat16(vB);
                        const u32 byte = bbase + (u32)p * STRIDE;
                        *(u32*)(smem + OFF_BH + byte) = packbf(hA, hB);
                        *(u32*)(smem + OFF_BL + byte) =
                            packbf(__float2bfloat16(vA - __bfloat162float(hA)),
                                   __float2bfloat16(vB - __bfloat162float(hB)));
                    } else {
                        poolA += vA; poolB += vB;
                    }
                }
                if (round == 3)
                    *(float2*)&((float*)(smem + OFF_G))[g * H + j] =
                        make_float2(poolA * (1.0f / 12.0f), poolB * (1.0f / 12.0f));
            }
            __syncthreads();                   // B / G ready
        }
    }

    // ---------------- head: g -> relu(g@W1+b1) -> @W2+b2 ----------------
    float* wv  = (float*)(smem + OFF_BH);      // [128][64] fp32; G/O1 live above 32768
    float* sG  = (float*)(smem + OFF_G);
    float* sO1 = (float*)(smem + OFF_O1);
    for (int i = tid; i < H * 64; i += THREADS) wv[i] = W_out1[i];
    __syncthreads();
    for (int i = tid; i < nb * 64; i += THREADS) {
        const int bb = i >> 6, m = i & 63;
        float s = b_out1[m];
        const float* gr = sG + bb * H;
        #pragma unroll 8
        for (int k = 0; k < H; k++) s = fmaf(gr[k], wv[k * 64 + m], s);
        sO1[i] = fmaxf(s, 0.f);
    }
    __syncthreads();
    if (tid < nb * 3) {
        const int bb = tid / 3, d = tid - bb * 3;
        float s = b_out2[d];
        const float* o1 = sO1 + bb * 64;
        #pragma unroll
        for (int m = 0; m < 64; m++) s = fmaf(o1[m], W_out2[m * 3 + d], s);
        out[(b0 + bb) * 3 + d] = s;
    }
}

extern "C" void kernel_launch(void* const* d_in, const int* in_sizes, int n_in,
                              void* d_out, int out_size)
{
    const float* x      = (const float*)d_in[0];
    const float* W_in   = (const float*)d_in[1];
    const float* b_in   = (const float*)d_in[2];
    const float* W_gcn  = (const float*)d_in[3];
    const float* b_gcn  = (const float*)d_in[4];
    const float* W_out1 = (const float*)d_in[5];
    const float* b_out1 = (const float*)d_in[6];
    const float* W_out2 = (const float*)d_in[7];
    const float* b_out2 = (const float*)d_in[8];
    float* out = (float*)d_out;

    const int B = in_sizes[0] / (P * DIN);
    const int blocks = (B + NB - 1) / NB;

    conv_w_kernel<<<64, 256>>>(W_in, W_gcn);

    cudaFuncSetAttribute(gnn_hmma11_kernel,
                         cudaFuncAttributeMaxDynamicSharedMemorySize, SMEM_BYTES);
    gnn_hmma11_kernel<<<blocks, THREADS, SMEM_BYTES>>>(
        x, b_in, b_gcn, W_out1, b_out1, W_out2, b_out2, out, B);
}